// round 17
// baseline (speedup 1.0000x reference)
#include <cuda_runtime.h>
#include <cuda_fp16.h>
#include <cstdint>

#define TE 128
#define NT 256
#define NNODE_MAX 50000

// Static device scratch (no runtime alloc)
__device__ __half g_W1abT[512 * 128];       // UV weights [n=512][k=128] (U|V)
__device__ __half g_W1T[256 * 256];         // edge L1 (diff|prod) [n=256][k=256]
__device__ __half g_W2T[128 * 256];         // [n=128][k=256]
__device__ __half g_UV[(size_t)NNODE_MAX * 512];  // per-node U|V, f16 (51.2 MB)

// ---------------- helpers ----------------
__device__ __forceinline__ uint32_t smem_u32(const void* p) {
    uint32_t a;
    asm("{ .reg .u64 t; cvta.to.shared.u64 t, %1; cvt.u32.u64 %0, t; }" : "=r"(a) : "l"(p));
    return a;
}
__device__ __forceinline__ uint32_t f2h2(float lo, float hi) {
    uint32_t r;
    asm("cvt.rn.f16x2.f32 %0, %1, %2;" : "=r"(r) : "f"(hi), "f"(lo));
    return r;
}
#define CP_ASYNC16(dst_u32, src_ptr) \
    asm volatile("cp.async.cg.shared.global [%0], [%1], 16;" :: "r"(dst_u32), "l"(src_ptr) : "memory")
#define CP_COMMIT() asm volatile("cp.async.commit_group;" ::: "memory")
#define CP_WAIT(n)  asm volatile("cp.async.wait_group %0;" :: "n"(n) : "memory")

__device__ __forceinline__ void mma16(float* c, const uint32_t* a, uint32_t b0, uint32_t b1) {
    asm volatile(
        "mma.sync.aligned.m16n8k16.row.col.f32.f16.f16.f32 "
        "{%0,%1,%2,%3}, {%4,%5,%6,%7}, {%8,%9}, {%0,%1,%2,%3};"
        : "+f"(c[0]), "+f"(c[1]), "+f"(c[2]), "+f"(c[3])
        : "r"(a[0]), "r"(a[1]), "r"(a[2]), "r"(a[3]), "r"(b0), "r"(b1));
}
__device__ __forceinline__ void ldm4(uint32_t* r, uint32_t addr) {
    asm volatile("ldmatrix.sync.aligned.m8n8.x4.shared.b16 {%0,%1,%2,%3}, [%4];"
                 : "=r"(r[0]), "=r"(r[1]), "=r"(r[2]), "=r"(r[3]) : "r"(addr));
}
__device__ __forceinline__ uint32_t habs_sub2(uint32_t a, uint32_t b) {
    __half2 r = __habs2(__hsub2(*(__half2*)&a, *(__half2*)&b));
    return *(uint32_t*)&r;
}
__device__ __forceinline__ uint32_t hmul2u(uint32_t a, uint32_t b) {
    __half2 r = __hmul2(*(__half2*)&a, *(__half2*)&b);
    return *(uint32_t*)&r;
}

// ---------------- smem layout (BYTE offsets), edge kernel ----------------
#define STRH   272       // [128 rows][128 f16 + 16B pad]
#define WBLK   34816     // one slot: [128 rows][STRH]
#define OFF_HI 0
#define OFF_HJ 34816
#define OFF_W  69632     // 4 slots; x1-h0 overlays slot0, x1-h1 overlays slot3
#define OFF_SRC 208896   // int[128]
#define OFF_DST 209408   // int[128]
#define OFF_B2  209920   // f32[128]
#define OFF_W3  210432   // f32[256]
#define OFF_B3  211456   // f32[2]
#define SMEM_BYTES 211464

// ---------------- prep 1: round + transpose weights ----------------
__global__ void prep_w(const float* __restrict__ W1, const float* __restrict__ W2) {
    int i = blockIdx.x * blockDim.x + threadIdx.x;
    if (i < 512 * 128) {                       // W1abT [n=512][k=128]
        int n = i >> 7, k = i & 127;
        float v = (n < 256) ? W1[k * 256 + n] : W1[(128 + k) * 256 + (n - 256)];
        g_W1abT[i] = __float2half_rn(v);
    } else if (i < 512 * 128 + 256 * 256) {    // W1T (diff|prod) [n=256][k=256]
        int j = i - 512 * 128;
        int n = j >> 8, k = j & 255;
        float v = (k < 128) ? W1[(256 + k) * 256 + n] : W1[(384 + (k - 128)) * 256 + n];
        g_W1T[j] = __float2half_rn(v);
    } else {
        int j = i - 512 * 128 - 256 * 256;     // W2T [n=128][k=256]
        if (j < 128 * 256) {
            int n = j >> 8, k = j & 255;
            g_W2T[j] = __float2half_rn(W2[k * 128 + n]);
        }
    }
}

// ---------------- prep 2: UV = node @ [W1a|W1b] (+b1 folded into U) ----------------
#define UV_SMEM 70656
__global__ __launch_bounds__(256, 1)
void uv_kernel(const float* __restrict__ node, const float* __restrict__ b1, int nnode) {
    extern __shared__ char smc[];
    const uint32_t smb = smem_u32(smc);
    float* s_b1 = (float*)(smc + 69632);
    const int tid = threadIdx.x, lane = tid & 31;
    const int g = lane >> 2, t = lane & 3;
    const int wid = tid >> 5, wm = wid >> 2, wn = wid & 3;
    const int nb = blockIdx.y;
    const int r0 = blockIdx.x * 128;

    #pragma unroll
    for (int i = 0; i < 16; i++) {
        int idx = tid + i * 256;
        int m = idx >> 5, c4 = idx & 31;
        int nr = min(r0 + m, nnode - 1);
        float4 v = ((const float4*)node)[(size_t)nr * 32 + c4];
        *(uint2*)(smc + m * STRH + c4 * 8) = make_uint2(f2h2(v.x, v.y), f2h2(v.z, v.w));
    }
    #pragma unroll
    for (int i = 0; i < 8; i++) {
        int idx = tid + i * 256;
        int n = idx >> 4, q = idx & 15;
        *(uint4*)(smc + 34816 + n * STRH + q * 16) =
            *(const uint4*)(g_W1abT + (size_t)(nb * 128 + n) * 128 + q * 8);
    }
    for (int i = tid; i < 256; i += 256) s_b1[i] = b1[i];
    __syncthreads();

    float acc[4][4][4];
    #pragma unroll
    for (int mt = 0; mt < 4; mt++)
        #pragma unroll
        for (int nt = 0; nt < 4; nt++) {
            int col = wn * 32 + nt * 8 + 2 * t;
            int gc = nb * 128 + col;
            float v0 = (nb < 2) ? s_b1[gc] : 0.f;
            float v1 = (nb < 2) ? s_b1[gc + 1] : 0.f;
            acc[mt][nt][0] = v0; acc[mt][nt][1] = v1;
            acc[mt][nt][2] = v0; acc[mt][nt][3] = v1;
        }

    const int aRow = lane & 15;
    const int aKoff = ((lane >> 4) << 3) * 2;
    const uint32_t aBase = smb + (wm * 64 + aRow) * STRH + aKoff;
    const int nl = ((lane >> 4) << 3) + (lane & 7);
    const uint32_t bOff = (lane & 8) ? 16u : 0u;

    #pragma unroll
    for (int s = 0; s < 8; s++) {
        uint32_t aF[4][4];
        #pragma unroll
        for (int mt = 0; mt < 4; mt++)
            ldm4(aF[mt], aBase + mt * (16 * STRH) + s * 32);
        uint32_t bF[2][4];
        #pragma unroll
        for (int np = 0; np < 2; np++)
            ldm4(bF[np], smb + 34816 + (wn * 32 + np * 16 + nl) * STRH + bOff + s * 32);
        #pragma unroll
        for (int mt = 0; mt < 4; mt++) {
            mma16(acc[mt][0], aF[mt], bF[0][0], bF[0][1]);
            mma16(acc[mt][1], aF[mt], bF[0][2], bF[0][3]);
            mma16(acc[mt][2], aF[mt], bF[1][0], bF[1][1]);
            mma16(acc[mt][3], aF[mt], bF[1][2], bF[1][3]);
        }
    }

    #pragma unroll
    for (int mt = 0; mt < 4; mt++) {
        int m = wm * 64 + mt * 16 + g;
        #pragma unroll
        for (int nt = 0; nt < 4; nt++) {
            int col = wn * 32 + nt * 8 + 2 * t;
            if (r0 + m < nnode)
                *(uint32_t*)((char*)g_UV + ((size_t)(r0 + m) * 512 + nb * 128 + col) * 2) =
                    f2h2(acc[mt][nt][0], acc[mt][nt][1]);
            if (r0 + m + 8 < nnode)
                *(uint32_t*)((char*)g_UV + ((size_t)(r0 + m + 8) * 512 + nb * 128 + col) * 2) =
                    f2h2(acc[mt][nt][2], acc[mt][nt][3]);
        }
    }
}

// ---------------- edge kernel: one 32KB weight block -> slot ----------------
__device__ __forceinline__ void issue_blk2(uint32_t smb, int tid, const __half* base, int slot) {
    #pragma unroll
    for (int j = 0; j < 8; j++) {
        int idx = tid + j * NT;           // 0..2047
        int n = idx >> 4, q = idx & 15;
        CP_ASYNC16(smb + OFF_W + slot * WBLK + n * STRH + q * 16,
                   base + (size_t)n * 256 + q * 8);
    }
}

// ---------------- main fused edge MLP (256 thr; warp grid 4M x 2N) ----------------
__global__ __launch_bounds__(NT, 1)
void edge_mlp_fuse(const float* __restrict__ node,
                   const int*   __restrict__ src,
                   const int*   __restrict__ dst,
                   const float* __restrict__ b2,
                   const float* __restrict__ W3,
                   const float* __restrict__ b3,
                   float* __restrict__ out, int E)
{
    extern __shared__ char smc[];
    const uint32_t smb = smem_u32(smc);
    float* smf = (float*)smc;
    int* s_src = (int*)(smc + OFF_SRC);
    int* s_dst = (int*)(smc + OFF_DST);

    const int tid = threadIdx.x, lane = tid & 31;
    const int g = lane >> 2, t = lane & 3;
    const int wid = tid >> 5;
    const int wm = wid >> 1, wn = wid & 1;       // 4(M:32 rows) x 2(N:64 cols)
    const int e0 = blockIdx.x * TE;
    const int nedge = min(TE, E - e0);

    // G1: h0 diff -> slot0, h0 prod -> slot1
    issue_blk2(smb, tid, g_W1T,       0);
    issue_blk2(smb, tid, g_W1T + 128, 1);
    CP_COMMIT();

    // gather h_i/h_j -> f16 smem; src/dst to smem
    #pragma unroll 4
    for (int i = 0; i < 16; i++) {
        int idx = tid + i * NT;
        int m = idx >> 5, c4 = idx & 31;
        int e = min(e0 + m, E - 1);
        int si = src[e], di = dst[e];
        if (c4 == 0) { s_src[m] = si; s_dst[m] = di; }
        float4 vi = ((const float4*)node)[(size_t)si * 32 + c4];
        float4 vj = ((const float4*)node)[(size_t)di * 32 + c4];
        *(uint2*)(smc + OFF_HI + m * STRH + c4 * 8) =
            make_uint2(f2h2(vi.x, vi.y), f2h2(vi.z, vi.w));
        *(uint2*)(smc + OFF_HJ + m * STRH + c4 * 8) =
            make_uint2(f2h2(vj.x, vj.y), f2h2(vj.z, vj.w));
    }
    for (int i = tid; i < 128; i += NT) smf[OFF_B2 / 4 + i] = b2[i];
    for (int i = tid; i < 256; i += NT) smf[OFF_W3 / 4 + i] = W3[i];
    if (tid < 2) smf[OFF_B3 / 4 + tid] = b3[tid];
    __syncthreads();

    const int aRow = lane & 15;
    const int aKoff = ((lane >> 4) << 3) * 2;
    const uint32_t hiBase = smb + OFF_HI + (wm * 32 + aRow) * STRH + aKoff;
    const uint32_t hjBase = smb + OFF_HJ + (wm * 32 + aRow) * STRH + aKoff;
    const int nl = ((lane >> 4) << 3) + (lane & 7);
    const uint32_t bOff = (lane & 8) ? 16u : 0u;

    float accL1[2][8][4];

    #pragma unroll
    for (int h = 0; h < 2; h++) {
        const int sd = h * 2, sp = h * 2 + 1;     // this half's diff/prod slots

        // wait this half's weight blocks, then prefetch next stage
        CP_WAIT(0);
        __syncthreads();
        if (h == 0) {   // G2: h1 blocks -> slots 2,3
            issue_blk2(smb, tid, g_W1T + 128 * 256,       2);
            issue_blk2(smb, tid, g_W1T + 128 * 256 + 128, 3);
            CP_COMMIT();
        } else {        // G3: L2 k0-127 -> slot1 (slot1 freed by sync above)
            issue_blk2(smb, tid, g_W2T, 1);
            CP_COMMIT();
        }

        // acc init = U[src] + V[dst] (b1 folded into U)
        #pragma unroll
        for (int mt = 0; mt < 2; mt++) {
            int r0 = wm * 32 + mt * 16 + g;
            const uint32_t* U0 = (const uint32_t*)(g_UV + (size_t)s_src[r0] * 512 + h * 128);
            const uint32_t* V0 = (const uint32_t*)(g_UV + (size_t)s_dst[r0] * 512 + 256 + h * 128);
            const uint32_t* U1 = (const uint32_t*)(g_UV + (size_t)s_src[r0 + 8] * 512 + h * 128);
            const uint32_t* V1 = (const uint32_t*)(g_UV + (size_t)s_dst[r0 + 8] * 512 + 256 + h * 128);
            #pragma unroll
            for (int nt = 0; nt < 8; nt++) {
                int co = wn * 32 + nt * 4 + t;
                float2 u0 = __half22float2(*(__half2*)&U0[co]);
                float2 v0 = __half22float2(*(__half2*)&V0[co]);
                float2 u1 = __half22float2(*(__half2*)&U1[co]);
                float2 v1 = __half22float2(*(__half2*)&V1[co]);
                accL1[mt][nt][0] = u0.x + v0.x; accL1[mt][nt][1] = u0.y + v0.y;
                accL1[mt][nt][2] = u1.x + v1.x; accL1[mt][nt][3] = u1.y + v1.y;
            }
        }

        // fused diff+prod pass: one fi/fj load feeds 32 mma per step
        #pragma unroll
        for (int s = 0; s < 8; s++) {
            uint32_t fi[2][4], fj[2][4], dF[2][4], pF[2][4];
            #pragma unroll
            for (int mt = 0; mt < 2; mt++) {
                ldm4(fi[mt], hiBase + mt * (16 * STRH) + s * 32);
                ldm4(fj[mt], hjBase + mt * (16 * STRH) + s * 32);
            }
            #pragma unroll
            for (int mt = 0; mt < 2; mt++)
                #pragma unroll
                for (int x = 0; x < 4; x++) {
                    dF[mt][x] = habs_sub2(fi[mt][x], fj[mt][x]);
                    pF[mt][x] = hmul2u(fi[mt][x], fj[mt][x]);
                }
            uint32_t bD[4][4], bP[4][4];
            #pragma unroll
            for (int np = 0; np < 4; np++) {
                uint32_t row = (wn * 64 + np * 16 + nl) * STRH + bOff + s * 32;
                ldm4(bD[np], smb + OFF_W + sd * WBLK + row);
                ldm4(bP[np], smb + OFF_W + sp * WBLK + row);
            }
            #pragma unroll
            for (int mt = 0; mt < 2; mt++)
                #pragma unroll
                for (int np = 0; np < 4; np++) {
                    mma16(accL1[mt][np * 2],     dF[mt], bD[np][0], bD[np][1]);
                    mma16(accL1[mt][np * 2 + 1], dF[mt], bD[np][2], bD[np][3]);
                    mma16(accL1[mt][np * 2],     pF[mt], bP[np][0], bP[np][1]);
                    mma16(accL1[mt][np * 2 + 1], pF[mt], bP[np][2], bP[np][3]);
                }
        }
        __syncthreads();

        // x1(h) = f16(relu(acc)) -> overlay slot (h0 -> slot0, h1 -> slot3)
        const int xs = (h == 0) ? 0 : 3;
        #pragma unroll
        for (int mt = 0; mt < 2; mt++) {
            int r = wm * 32 + mt * 16 + g;
            #pragma unroll
            for (int nt = 0; nt < 8; nt++) {
                int col = wn * 64 + nt * 8 + 2 * t;
                float* A = accL1[mt][nt];
                *(uint32_t*)(smc + OFF_W + xs * WBLK + r * STRH + col * 2) =
                    f2h2(fmaxf(A[0], 0.f), fmaxf(A[1], 0.f));
                *(uint32_t*)(smc + OFF_W + xs * WBLK + (r + 8) * STRH + col * 2) =
                    f2h2(fmaxf(A[2], 0.f), fmaxf(A[3], 0.f));
            }
        }
        if (h == 1) {   // G4: L2 k128-255 -> slot2 (freed by sync above)
            issue_blk2(smb, tid, g_W2T + 128, 2);
            CP_COMMIT();
        }
    }

    // ================= layer 2: two passes (W slot1/A slot0, W slot2/A slot3) =================
    float accL2[2][8][4];
    #pragma unroll
    for (int mt = 0; mt < 2; mt++)
        #pragma unroll
        for (int nt = 0; nt < 8; nt++) {
            int col = wn * 64 + nt * 8 + 2 * t;
            float v0 = smf[OFF_B2 / 4 + col], v1 = smf[OFF_B2 / 4 + col + 1];
            accL2[mt][nt][0] = v0; accL2[mt][nt][1] = v1;
            accL2[mt][nt][2] = v0; accL2[mt][nt][3] = v1;
        }

    #pragma unroll
    for (int p = 0; p < 2; p++) {
        const int sw = (p == 0) ? 1 : 2;     // W slot
        const int sa = (p == 0) ? 0 : 3;     // x1 slot
        if (p == 0) CP_WAIT(1); else CP_WAIT(0);
        __syncthreads();

        const uint32_t aB = smb + OFF_W + sa * WBLK + (wm * 32 + aRow) * STRH + aKoff;
        #pragma unroll
        for (int s = 0; s < 8; s++) {
            uint32_t aF[2][4];
            #pragma unroll
            for (int mt = 0; mt < 2; mt++)
                ldm4(aF[mt], aB + mt * (16 * STRH) + s * 32);
            uint32_t bF[4][4];
            #pragma unroll
            for (int np = 0; np < 4; np++)
                ldm4(bF[np], smb + OFF_W + sw * WBLK
                             + (wn * 64 + np * 16 + nl) * STRH + bOff + s * 32);
            #pragma unroll
            for (int mt = 0; mt < 2; mt++)
                #pragma unroll
                for (int np = 0; np < 4; np++) {
                    mma16(accL2[mt][np * 2],     aF[mt], bF[np][0], bF[np][1]);
                    mma16(accL2[mt][np * 2 + 1], aF[mt], bF[np][2], bF[np][3]);
                }
        }
    }
    __syncthreads();

    // ================= layer 3: register relu.W3 + quad shuffle-reduce =================
    float* s_red = (float*)(smc + OFF_HI);   // hi region dead: [128 r][2 wn][2 c]
    #pragma unroll
    for (int mt = 0; mt < 2; mt++) {
        int r = wm * 32 + mt * 16 + g;
        float p00 = 0.f, p01 = 0.f, p10 = 0.f, p11 = 0.f;
        #pragma unroll
        for (int nt = 0; nt < 8; nt++) {
            float* A = accL2[mt][nt];
            int col = wn * 64 + nt * 8 + 2 * t;
            float w00 = smf[OFF_W3 / 4 + 2 * col],     w01 = smf[OFF_W3 / 4 + 2 * col + 1];
            float w10 = smf[OFF_W3 / 4 + 2 * col + 2], w11 = smf[OFF_W3 / 4 + 2 * col + 3];
            float x0 = fmaxf(A[0], 0.f), x1v = fmaxf(A[1], 0.f);
            float x2v = fmaxf(A[2], 0.f), x3v = fmaxf(A[3], 0.f);
            p00 += x0 * w00 + x1v * w10;
            p01 += x0 * w01 + x1v * w11;
            p10 += x2v * w00 + x3v * w10;
            p11 += x2v * w01 + x3v * w11;
        }
        p00 += __shfl_xor_sync(0xFFFFFFFFu, p00, 1);
        p00 += __shfl_xor_sync(0xFFFFFFFFu, p00, 2);
        p01 += __shfl_xor_sync(0xFFFFFFFFu, p01, 1);
        p01 += __shfl_xor_sync(0xFFFFFFFFu, p01, 2);
        p10 += __shfl_xor_sync(0xFFFFFFFFu, p10, 1);
        p10 += __shfl_xor_sync(0xFFFFFFFFu, p10, 2);
        p11 += __shfl_xor_sync(0xFFFFFFFFu, p11, 1);
        p11 += __shfl_xor_sync(0xFFFFFFFFu, p11, 2);
        if (t == 0) {
            s_red[r * 4 + wn * 2 + 0] = p00;
            s_red[r * 4 + wn * 2 + 1] = p01;
            s_red[(r + 8) * 4 + wn * 2 + 0] = p10;
            s_red[(r + 8) * 4 + wn * 2 + 1] = p11;
        }
    }
    __syncthreads();

    {
        int row = tid >> 1, cc = tid & 1;
        float sum = smf[OFF_B3 / 4 + cc]
                  + s_red[row * 4 + cc] + s_red[row * 4 + 2 + cc];
        if (row < nedge) out[(size_t)(e0 + row) * 2 + cc] = sum;
    }
}

extern "C" void kernel_launch(void* const* d_in, const int* in_sizes, int n_in,
                              void* d_out, int out_size)
{
    const float* node = (const float*)d_in[0];
    const int*   src  = (const int*)  d_in[1];
    const int*   dst  = (const int*)  d_in[2];
    const float* W1   = (const float*)d_in[3];
    const float* b1   = (const float*)d_in[4];
    const float* W2   = (const float*)d_in[5];
    const float* b2   = (const float*)d_in[6];
    const float* W3   = (const float*)d_in[7];
    const float* b3   = (const float*)d_in[8];
    float* out = (float*)d_out;

    const int E = in_sizes[1];
    const int nnode = in_sizes[0] / 128;

    {   // prep 1: weight rounding/transpose
        int total = 512 * 128 + 256 * 256 + 128 * 256;
        prep_w<<<(total + 255) / 256, 256>>>(W1, W2);
    }
    {   // prep 2: UV = node @ [W1a|W1b] + [b1|0]
        cudaFuncSetAttribute(uv_kernel,
                             cudaFuncAttributeMaxDynamicSharedMemorySize, UV_SMEM);
        dim3 grid((nnode + 127) / 128, 4);
        uv_kernel<<<grid, 256, UV_SMEM>>>(node, b1, nnode);
    }

    cudaFuncSetAttribute(edge_mlp_fuse,
                         cudaFuncAttributeMaxDynamicSharedMemorySize, SMEM_BYTES);
    const int grid = (E + TE - 1) / TE;
    edge_mlp_fuse<<<grid, NT, SMEM_BYTES>>>(node, src, dst, b2, W3, b3, out, E);
}